// round 9
// baseline (speedup 1.0000x reference)
#include <cuda_runtime.h>

// MMSolver: 128x128 LLG micromagnetics, 100 relax + 256 driven RK4 steps.
// Persistent kernel, 128 CTAs (8x16 tile each), superstep = 2 RK4 steps
// (8 stencil stages, halo 8) on a 24x32 region in smem. Relax-skip precheck (R6).
// R7: NO intra-superstep CTA barriers. Warp = region row; W/E neighbors via
// warp shuffle (lockstep), N/S via smem guarded by PER-LANE acquire/release
// flags (st.release.cta / ld.acquire.cta). Rows pipeline as a wavefront.
// Superstep-start neighbor wait is per-thread on the source CTA's global flag.
// One __syncthreads per superstep (before global flag release; also protects
// smem buffer reuse across supersteps).

#define NXY 128
#define TI 8
#define TJ 16
#define HALO 8
#define RI (TI + 2*HALO)      // 24
#define RJ (TJ + 2*HALO)      // 32
#define NCTA 128
#define NTHREADS (RI*RJ)      // 768
#define RELAXN 100
#define TSIG 256
#define NSS_FULL ((RELAXN + TSIG)/2)   // 178
#define NSS_SKIP (TSIG/2)              // 128
#define FSTR 32                        // 128B spacing for global flags

#define HH      0.017595f                        // GAMMA*DT
#define CS      0.001f                           // C_SOT
#define MU0F    1.2566370614359173e-06f
#define CEXN    (2.0f*1.3e-11f/(5e-9f*5e-9f))   // 2*A_EX/DX^2

__device__ float g_m[2][3][NXY][NXY];
__device__ unsigned int g_flag[NCTA * FSTR];
__device__ int g_need[NCTA];

__device__ __forceinline__ unsigned ld_acq_cta_shared(const unsigned* p) {
    unsigned v;
    unsigned a = (unsigned)__cvta_generic_to_shared(p);
    asm volatile("ld.acquire.cta.shared.u32 %0, [%1];" : "=r"(v) : "r"(a));
    return v;
}
__device__ __forceinline__ void st_rel_cta_shared(unsigned* p, unsigned v) {
    unsigned a = (unsigned)__cvta_generic_to_shared(p);
    asm volatile("st.release.cta.shared.u32 [%0], %1;" :: "r"(a), "r"(v) : "memory");
}
__device__ __forceinline__ unsigned ld_acq_gpu(const unsigned* p) {
    unsigned v;
    asm volatile("ld.acquire.gpu.u32 %0, [%1];" : "=r"(v) : "l"(p));
    return v;
}

// Precheck: relax phase is an exact no-op iff B_ext.x == 0 and B_ext.z == 0
// everywhere (m stays exactly y-hat).
__global__ void __launch_bounds__(128, 1)
precheck_kernel(const float* __restrict__ B_ext)
{
    __shared__ int f;
    if (threadIdx.x == 0) f = 0;
    __syncthreads();
    const int i = blockIdx.x * 128 + threadIdx.x;
    const float bx = B_ext[i];
    const float bz = B_ext[2 * NXY * NXY + i];
    if (bx != 0.f || bz != 0.f) f = 1;
    __syncthreads();
    if (threadIdx.x == 0) g_need[blockIdx.x] = f;
}

__global__ void __launch_bounds__(NTHREADS, 1)
mm_kernel(const float* __restrict__ signal,
          const float* __restrict__ B_ext,
          const float* __restrict__ Msat,
          const int*   __restrict__ src_idx,
          const int*   __restrict__ probe_idx,
          float*       __restrict__ out)
{
    __shared__ float4   sm[2][RI][RJ];     // (x,y,z,pad) per cell
    __shared__ unsigned sflag[RI][RJ];     // per-lane data-ready flags
    __shared__ unsigned s_base;
    const unsigned FULL = 0xFFFFFFFFu;

    const int tid = threadIdx.x;
    const int me  = blockIdx.x;
    if (tid == 0) s_base = *(volatile unsigned int*)&g_flag[me * FSTR];

    const int ri = tid >> 5;        // region row 0..23 (warp id)
    const int rj = tid & 31;        // region col 0..31 (lane)
    sflag[ri][rj] = 0;

    // uniform decision: run relax phase or skip it (barrier also covers
    // s_base and sflag init)
    const int need_relax = __syncthreads_or(tid < NCTA ? g_need[tid] : 0);
    const int step0 = need_relax ? 0 : RELAXN;
    const int nss   = need_relax ? NSS_FULL : NSS_SKIP;

    const int bi = me >> 3;         // 0..15
    const int bj = me & 7;          // 0..7
    const int gi = bi * TI - HALO + ri;
    const int gj = bj * TJ - HALO + rj;
    const int gci = min(max(gi, 0), NXY - 1);
    const int gcj = min(max(gj, 0), NXY - 1);
    const int gg  = gci * NXY + gcj;

    // N/S region rows, clamped at the DOMAIN boundary (edge-replicate -> own row)
    const int riN = (gi <= 0)       ? ri : ri - 1;
    const int riS = (gi >= NXY - 1) ? ri : ri + 1;
    // W/E domain-edge ownership (override shuffle with own value)
    const bool ownW = (gj == 0);
    const bool ownE = (gj == NXY - 1);

    // last stage this row computes: q <= min(ri-1, 22-ri), capped at 7
    const int rowmax = min(min(ri - 1, (RI - 2) - ri), 7);

    // source CTA of this thread's (clamped) cell, for superstep-start wait
    const int sCTA = (gci >> 3) * 8 + (gcj >> 4);

    // per-cell statics (clamped loads; garbage cells get consistent clones)
    const float Bx   = B_ext[gg];
    const float By   = B_ext[NXY*NXY + gg];
    const float Bzs  = B_ext[2*NXY*NXY + gg];
    const float msat = Msat[gg];
    const float cex  = CEXN / msat;
    const float dem  = -MU0F * msat;

    // src slot: last match wins (JAX .set scatter semantics)
    int srcslot = -1;
    #pragma unroll
    for (int s = 0; s < 2; s++)
        if (src_idx[2*s] == gi && src_idx[2*s + 1] == gj) srcslot = s;

    const bool is_tile = (ri >= HALO && ri < HALO + TI && rj >= HALO && rj < HALO + TJ);
    int probemask = 0;
    if (is_tile) {
        #pragma unroll
        for (int p = 0; p < 4; p++)
            if (probe_idx[2*p] == gi && probe_idx[2*p + 1] == gj) probemask |= 1 << p;
    }
    float probe_base = 0.f;   // exact when relax phase is skipped

    const unsigned base = s_base;

    float cmx, cmy, cmz;    // current stage value
    float m0x, m0y, m0z;    // value at start of current RK4 step
    float ax = 0.f, ay = 0.f, az = 0.f;

    for (int ss = 0; ss < nss; ++ss) {
        const unsigned sbase = 1u + (unsigned)ss * 9u;   // flag value for data 0

        // ---- per-thread wait on source CTA, then load region ----
        if (ss == 0) {
            cmx = 0.f; cmy = 1.f; cmz = 0.f;   // m_init (= post-relax state if skipping)
        } else {
            if (sCTA != me) {
                const unsigned tgt = base + (unsigned)ss;
                while ((int)(ld_acq_gpu(&g_flag[sCTA * FSTR]) - tgt) < 0) { }
            }
            const float* gmr = &g_m[(ss - 1) & 1][0][0][0];
            cmx = __ldcg(gmr + gg);
            cmy = __ldcg(gmr + NXY*NXY + gg);
            cmz = __ldcg(gmr + 2*NXY*NXY + gg);
        }
        // publish data 0 (buffer reuse safe: __syncthreads at end of prev superstep)
        sm[0][ri][rj] = make_float4(cmx, cmy, cmz, 0.f);
        st_rel_cta_shared(&sflag[ri][rj], sbase);
        m0x = cmx; m0y = cmy; m0z = cmz;

        // preload driven-field z for the 2 steps of this superstep
        float bzstep[2]; bzstep[0] = Bzs; bzstep[1] = Bzs;
        if (srcslot >= 0) {
            #pragma unroll
            for (int s = 0; s < 2; s++) {
                const int step = step0 + ss * 2 + s;
                if (step >= RELAXN)
                    bzstep[s] = __ldg(&signal[(step - RELAXN) * 2 + srcslot]);
            }
        }

        #pragma unroll
        for (int q = 0; q < 8; ++q) {
            if (q <= rowmax) {
                const int s  = q >> 2;
                const int st = q & 3;
                const int step = step0 + ss * 2 + s;
                const float alpha = (step < RELAXN) ? 0.5f : 0.02f;
                const float ncoef = -1.0f / (1.0f + alpha * alpha);
                const float bzd = bzstep[s];
                const unsigned fv = sbase + (unsigned)q;

                // wait for N/S rows' data q (per-lane flags)
                while ((int)(ld_acq_cta_shared(&sflag[riN][rj]) - fv) < 0) { }
                while ((int)(ld_acq_cta_shared(&sflag[riS][rj]) - fv) < 0) { }
                const float4 vN = sm[q & 1][riN][rj];
                const float4 vS = sm[q & 1][riS][rj];

                // W/E from lockstep warp registers
                float wx = __shfl_up_sync(FULL, cmx, 1);
                float wy = __shfl_up_sync(FULL, cmy, 1);
                float wz = __shfl_up_sync(FULL, cmz, 1);
                float ex = __shfl_down_sync(FULL, cmx, 1);
                float ey = __shfl_down_sync(FULL, cmy, 1);
                float ez = __shfl_down_sync(FULL, cmz, 1);
                wx = ownW ? cmx : wx;  wy = ownW ? cmy : wy;  wz = ownW ? cmz : wz;
                ex = ownE ? cmx : ex;  ey = ownE ? cmy : ey;  ez = ownE ? cmz : ez;

                const float lx = (vN.x + vS.x) + (wx + ex) - 4.f * cmx;
                const float ly = (vN.y + vS.y) + (wy + ey) - 4.f * cmy;
                const float lz = (vN.z + vS.z) + (wz + ez) - 4.f * cmz;

                const float bx = Bx  + cex * lx;
                const float by = By  + cex * ly;
                const float bz = bzd + cex * lz + dem * cmz;
                // c = m x B
                const float cx = cmy * bz - cmz * by;
                const float cy = cmz * bx - cmx * bz;
                const float cz = cmx * by - cmy * bx;
                // d = m x c
                const float dx = cmy * cz - cmz * cy;
                const float dy = cmz * cx - cmx * cz;
                const float dz = cmx * cy - cmy * cx;
                // k = sot + ncoef*(c + alpha*d)
                const float kx =  CS * (cmx * cmy)             + ncoef * (cx + alpha * dx);
                const float ky = -CS * (cmx * cmx + cmz * cmz) + ncoef * (cy + alpha * dy);
                const float kz =  CS * (cmy * cmz)             + ncoef * (cz + alpha * dz);

                if (st == 0) {
                    ax = kx; ay = ky; az = kz;
                    cmx = m0x + (0.5f * HH) * kx;
                    cmy = m0y + (0.5f * HH) * ky;
                    cmz = m0z + (0.5f * HH) * kz;
                } else if (st < 3) {
                    ax += 2.f * kx; ay += 2.f * ky; az += 2.f * kz;
                    const float cc = (st == 2) ? HH : (0.5f * HH);
                    cmx = m0x + cc * kx;
                    cmy = m0y + cc * ky;
                    cmz = m0z + cc * kz;
                } else {
                    cmx = m0x + (HH / 6.f) * (ax + kx);
                    cmy = m0y + (HH / 6.f) * (ay + ky);
                    cmz = m0z + (HH / 6.f) * (az + kz);
                    m0x = cmx; m0y = cmy; m0z = cmz;   // RK4 step complete
                }

                if (q < 7) {   // publish data q+1 (stage-7 result never re-read)
                    sm[(q + 1) & 1][ri][rj] = make_float4(cmx, cmy, cmz, 0.f);
                    st_rel_cta_shared(&sflag[ri][rj], fv + 1u);
                }

                // probe readout after each completed RK4 step
                if (st == 3 && probemask) {
                    if (step == RELAXN - 1) {
                        probe_base = m0z;
                    } else if (step >= RELAXN) {
                        const float v = (m0z - probe_base) * msat;
                        const int t = step - RELAXN;
                        #pragma unroll
                        for (int p = 0; p < 4; p++)
                            if ((probemask >> p) & 1) out[t * 4 + p] = v;
                    }
                }
            }
        }

        // ---- write back owned tile (double-buffered) ----
        {
            float* gmw = &g_m[ss & 1][0][0][0];
            if (is_tile) {
                const int g = gi * NXY + gj;
                __stcg(gmw + g,               m0x);
                __stcg(gmw + NXY*NXY + g,     m0y);
                __stcg(gmw + 2*NXY*NXY + g,   m0z);
            }
        }
        // single CTA barrier: all writes done + smem buffers free for reuse
        __syncthreads();
        if (ss < nss - 1 && tid == 0) {
            __threadfence();
            atomicExch(&g_flag[me * FSTR], base + (unsigned)ss + 1u);
        }
    }
}

extern "C" void kernel_launch(void* const* d_in, const int* in_sizes, int n_in,
                              void* d_out, int out_size)
{
    (void)in_sizes; (void)n_in; (void)out_size;
    precheck_kernel<<<NCTA, 128>>>((const float*)d_in[1]);
    mm_kernel<<<NCTA, NTHREADS>>>(
        (const float*)d_in[0],   // signal (1,256,2)
        (const float*)d_in[1],   // B_ext  (1,3,128,128)
        (const float*)d_in[2],   // Msat   (1,1,128,128)
        (const int*)d_in[3],     // src_idx (2,2)
        (const int*)d_in[4],     // probe_idx (4,2)
        (float*)d_out);          // (1,256,4)
}

// round 10
// speedup vs baseline: 2.8663x; 2.8663x over previous
#include <cuda_runtime.h>

// MMSolver: 128x128 LLG micromagnetics, 100 relax + 256 driven RK4 steps.
// Persistent kernel, 128 CTAs (8x16 tile each), superstep = 2 RK4 steps
// (8 stencil stages, halo 8) on a 24x32 region in smem, shrink-predicated,
// float4-packed smem, per-stage __syncthreads (R6-proven body).
// Relax-skip precheck (R6): relax phase is an exact no-op iff B_ext.x==0 and
// B_ext.z==0 everywhere (m stays exactly y-hat).
// R9 (vs R6 winner):
//  * superstep-start wait is PER-THREAD (halo threads ld.acquire.gpu-poll the
//    source CTA's flag) -- removes one CTA barrier + poll convoy.
//  * tile threads reuse their m0 registers instead of reloading from global.
//  * flag release via st.release.gpu (replaces __threadfence + atomicExch).

#define NXY 128
#define TI 8
#define TJ 16
#define HALO 8
#define RI (TI + 2*HALO)      // 24
#define RJ (TJ + 2*HALO)      // 32
#define NCTA 128
#define NTHREADS (RI*RJ)      // 768
#define RELAXN 100
#define TSIG 256
#define NSS_FULL ((RELAXN + TSIG)/2)   // 178
#define NSS_SKIP (TSIG/2)              // 128
#define FSTR 32                        // 128B spacing for global flags

#define HH      0.017595f                        // GAMMA*DT
#define CS      0.001f                           // C_SOT
#define MU0F    1.2566370614359173e-06f
#define CEXN    (2.0f*1.3e-11f/(5e-9f*5e-9f))   // 2*A_EX/DX^2

__device__ float g_m[2][3][NXY][NXY];
__device__ unsigned int g_flag[NCTA * FSTR];
__device__ int g_need[NCTA];

__device__ __forceinline__ unsigned ld_acq_gpu(const unsigned* p) {
    unsigned v;
    asm volatile("ld.acquire.gpu.u32 %0, [%1];" : "=r"(v) : "l"(p));
    return v;
}
__device__ __forceinline__ void st_rel_gpu(unsigned* p, unsigned v) {
    asm volatile("st.release.gpu.u32 [%0], %1;" :: "l"(p), "r"(v) : "memory");
}

// Precheck: any nonzero B_ext.x or B_ext.z anywhere?
__global__ void __launch_bounds__(128, 1)
precheck_kernel(const float* __restrict__ B_ext)
{
    __shared__ int f;
    if (threadIdx.x == 0) f = 0;
    __syncthreads();
    const int i = blockIdx.x * 128 + threadIdx.x;
    const float bx = B_ext[i];
    const float bz = B_ext[2 * NXY * NXY + i];
    if (bx != 0.f || bz != 0.f) f = 1;
    __syncthreads();
    if (threadIdx.x == 0) g_need[blockIdx.x] = f;
}

__global__ void __launch_bounds__(NTHREADS, 1)
mm_kernel(const float* __restrict__ signal,
          const float* __restrict__ B_ext,
          const float* __restrict__ Msat,
          const int*   __restrict__ src_idx,
          const int*   __restrict__ probe_idx,
          float*       __restrict__ out)
{
    __shared__ float4 sm[2][RI][RJ];     // (x,y,z,pad) per cell
    __shared__ unsigned s_base;

    const int tid = threadIdx.x;
    const int me  = blockIdx.x;
    if (tid == 0) s_base = *(volatile unsigned int*)&g_flag[me * FSTR];

    // uniform decision: run relax phase or skip it (barrier also covers s_base)
    const int need_relax = __syncthreads_or(tid < NCTA ? g_need[tid] : 0);
    const int step0 = need_relax ? 0 : RELAXN;
    const int nss   = need_relax ? NSS_FULL : NSS_SKIP;

    const int ri = tid >> 5;        // region row 0..23 (warp id)
    const int rj = tid & 31;        // region col 0..31 (lane)
    const int bi = me >> 3;         // 0..15
    const int bj = me & 7;          // 0..7
    const int gi = bi * TI - HALO + ri;
    const int gj = bj * TJ - HALO + rj;
    const bool in_dom = (gi >= 0 && gi < NXY && gj >= 0 && gj < NXY);
    const int gci = min(max(gi, 0), NXY - 1);
    const int gcj = min(max(gj, 0), NXY - 1);
    const int gg  = gci * NXY + gcj;

    // neighbor region indices, clamped at the DOMAIN boundary (edge-replicate)
    const int riN = (gi <= 0)       ? ri : ri - 1;
    const int riS = (gi >= NXY - 1) ? ri : ri + 1;
    const int rjW = (gj <= 0)       ? rj : rj - 1;
    const int rjE = (gj >= NXY - 1) ? rj : rj + 1;

    // source CTA of this thread's (clamped) cell
    const int sCTA = (gci >> 3) * 8 + (gcj >> 4);
    const bool is_tile = (ri >= HALO && ri < HALO + TI && rj >= HALO && rj < HALO + TJ);
    // threads that must reload from global each superstep:
    //  - halo threads sourcing a NEIGHBOR CTA (wait on that CTA's flag)
    //  - edge-CTA out-of-domain threads whose clamped cell is in OWN tile
    //    (no wait needed: own writeback precedes own flag/barrier)
    const bool needs_load = !is_tile;
    const bool needs_wait = (sCTA != me);

    // per-cell statics
    float Bx = 0.f, By = 0.f, Bzs = 0.f, cex = 0.f, dem = 0.f, msat = 0.f;
    if (in_dom) {
        Bx   = B_ext[gg];
        By   = B_ext[NXY*NXY + gg];
        Bzs  = B_ext[2*NXY*NXY + gg];
        msat = Msat[gg];
        cex  = CEXN / msat;
        dem  = -MU0F * msat;
    }

    // src slot: last match wins (JAX .set scatter semantics)
    int srcslot = -1;
    #pragma unroll
    for (int s = 0; s < 2; s++)
        if (src_idx[2*s] == gi && src_idx[2*s + 1] == gj) srcslot = s;

    int probemask = 0;
    if (is_tile && in_dom) {
        #pragma unroll
        for (int p = 0; p < 4; p++)
            if (probe_idx[2*p] == gi && probe_idx[2*p + 1] == gj) probemask |= 1 << p;
    }
    float probe_base = 0.f;   // exact when relax phase is skipped

    // precomputed shrink-window predicate, one bit per stage q=0..7
    unsigned cmask = 0;
    #pragma unroll
    for (int q = 0; q < 8; q++)
        if (in_dom && ri > q && ri < RI - 1 - q && rj > q && rj < RJ - 1 - q)
            cmask |= 1u << q;

    const unsigned base = s_base;

    float cmx, cmy, cmz;    // current stage value
    float m0x = 0.f, m0y = 1.f, m0z = 0.f;   // value at start of current RK4 step
    int cur = 0;

    for (int ss = 0; ss < nss; ++ss) {
        // ---- acquire source data (per-thread), then publish region to smem ----
        if (ss == 0) {
            cmx = 0.f; cmy = 1.f; cmz = 0.f;   // m_init (= post-relax state if skipping)
        } else if (needs_load) {
            if (needs_wait) {
                const unsigned tgt = base + (unsigned)ss;
                while ((int)(ld_acq_gpu(&g_flag[sCTA * FSTR]) - tgt) < 0) { }
            }
            const float* gmr = &g_m[(ss - 1) & 1][0][0][0];
            cmx = __ldcg(gmr + gg);
            cmy = __ldcg(gmr + NXY*NXY + gg);
            cmz = __ldcg(gmr + 2*NXY*NXY + gg);
        } else {
            cmx = m0x; cmy = m0y; cmz = m0z;   // tile thread: registers are current
        }
        sm[cur][ri][rj] = make_float4(cmx, cmy, cmz, 0.f);
        m0x = cmx; m0y = cmy; m0z = cmz;

        // preload driven-field z for the 2 steps of this superstep
        float bzstep[2]; bzstep[0] = Bzs; bzstep[1] = Bzs;
        if (srcslot >= 0) {
            #pragma unroll
            for (int s = 0; s < 2; s++) {
                const int step = step0 + ss * 2 + s;
                if (step >= RELAXN)
                    bzstep[s] = __ldg(&signal[(step - RELAXN) * 2 + srcslot]);
            }
        }
        __syncthreads();   // all sm[cur] written (also: smem buffers free for reuse)

        #pragma unroll
        for (int s = 0; s < 2; ++s) {
            const int step = step0 + ss * 2 + s;
            const bool relax = (step < RELAXN);
            const float alpha = relax ? 0.5f : 0.02f;
            const float ncoef = -1.0f / (1.0f + alpha * alpha);
            const float bzd = bzstep[s];

            float ax = 0.f, ay = 0.f, az = 0.f;   // k1 + 2k2 + 2k3

            #pragma unroll
            for (int st = 0; st < 4; ++st) {
                const int q = s * 4 + st;
                const bool comp = (cmask >> q) & 1;
                const int nxt = cur ^ 1;
                if (comp) {
                    const float4 vN = sm[cur][riN][rj];
                    const float4 vS = sm[cur][riS][rj];
                    const float4 vW = sm[cur][ri][rjW];
                    const float4 vE = sm[cur][ri][rjE];
                    const float lx = (vN.x + vS.x) + (vW.x + vE.x) - 4.f * cmx;
                    const float ly = (vN.y + vS.y) + (vW.y + vE.y) - 4.f * cmy;
                    const float lz = (vN.z + vS.z) + (vW.z + vE.z) - 4.f * cmz;
                    const float bx = Bx  + cex * lx;
                    const float by = By  + cex * ly;
                    const float bz = bzd + cex * lz + dem * cmz;
                    // c = m x B
                    const float cx = cmy * bz - cmz * by;
                    const float cy = cmz * bx - cmx * bz;
                    const float cz = cmx * by - cmy * bx;
                    // d = m x c
                    const float dx = cmy * cz - cmz * cy;
                    const float dy = cmz * cx - cmx * cz;
                    const float dz = cmx * cy - cmy * cx;
                    // k = sot + ncoef*(c + alpha*d)
                    const float kx =  CS * (cmx * cmy)             + ncoef * (cx + alpha * dx);
                    const float ky = -CS * (cmx * cmx + cmz * cmz) + ncoef * (cy + alpha * dy);
                    const float kz =  CS * (cmy * cmz)             + ncoef * (cz + alpha * dz);

                    if (st < 3) {
                        const float w = (st == 0) ? 1.f : 2.f;
                        ax += w * kx; ay += w * ky; az += w * kz;
                        const float cc = (st == 2) ? HH : (0.5f * HH);
                        cmx = m0x + cc * kx;
                        cmy = m0y + cc * ky;
                        cmz = m0z + cc * kz;
                    } else {
                        cmx = m0x + (HH / 6.f) * (ax + kx);
                        cmy = m0y + (HH / 6.f) * (ay + ky);
                        cmz = m0z + (HH / 6.f) * (az + kz);
                        m0x = cmx; m0y = cmy; m0z = cmz;   // RK4 step complete
                    }
                    if (!(s == 1 && st == 3)) {   // final stage never re-read from smem
                        sm[nxt][ri][rj] = make_float4(cmx, cmy, cmz, 0.f);
                    }
                }
                cur = nxt;
                if (!(s == 1 && st == 3))   // no smem written at final stage
                    __syncthreads();
            }

            // probe readout (tile cells valid after every step)
            if (probemask) {
                if (step == RELAXN - 1) {
                    probe_base = m0z;
                } else if (step >= RELAXN) {
                    const float v = (m0z - probe_base) * msat;
                    const int t = step - RELAXN;
                    #pragma unroll
                    for (int p = 0; p < 4; p++)
                        if ((probemask >> p) & 1) out[t * 4 + p] = v;
                }
            }
        }

        // ---- write back owned tile (double-buffered), release flag ----
        if (is_tile) {
            float* gmw = &g_m[ss & 1][0][0][0];
            const int g = gi * NXY + gj;
            __stcg(gmw + g,               m0x);
            __stcg(gmw + NXY*NXY + g,     m0y);
            __stcg(gmw + 2*NXY*NXY + g,   m0z);
        }
        __syncthreads();     // all tile writes done before release
        if (ss < nss - 1 && tid == 0)
            st_rel_gpu(&g_flag[me * FSTR], base + (unsigned)ss + 1u);
    }
}

extern "C" void kernel_launch(void* const* d_in, const int* in_sizes, int n_in,
                              void* d_out, int out_size)
{
    (void)in_sizes; (void)n_in; (void)out_size;
    precheck_kernel<<<NCTA, 128>>>((const float*)d_in[1]);
    mm_kernel<<<NCTA, NTHREADS>>>(
        (const float*)d_in[0],   // signal (1,256,2)
        (const float*)d_in[1],   // B_ext  (1,3,128,128)
        (const float*)d_in[2],   // Msat   (1,1,128,128)
        (const int*)d_in[3],     // src_idx (2,2)
        (const int*)d_in[4],     // probe_idx (4,2)
        (float*)d_out);          // (1,256,4)
}